// round 2
// baseline (speedup 1.0000x reference)
#include <cuda_runtime.h>

// SMPL nearest-neighbor skinning.
// Inputs (metadata order):
//   d_in[0] xyz               [n,3]  f32
//   d_in[1] rotation          [n,4]  f32 (quaternion, unnormalized)
//   d_in[2] smpl_verts        [nv,3] f32
//   d_in[3] skinning_weights  [nv,24] f32
//   d_in[4] bone_transforms   [24,4,4] f32
// Output (flat f32, tuple order):
//   [0,        3n)  x_bar
//   [3n,      12n)  rotation_bar
//   [12n,     28n)  T_fwd
//
// Argmin emulates the reference float32 rounding EXACTLY:
//   d2_j = ( sx - 2*dot_j ) + sv_j
//   dot_j = fma(x2,v2, fma(x1,v1, fma(x0,v0, 0)))   (SGEMM FFMA chain)
//   sv_j  = (v0*v0 + v1*v1) + v2*v2                 (mul/add, no contraction)
//   (sx - 2*dot) == fma(-2, dot, sx)  bit-exactly, since 2*dot is exact.

__global__ void __launch_bounds__(256, 2) smpl_nn_kernel(
    const float* __restrict__ xyz,
    const float* __restrict__ rot,
    const float* __restrict__ verts,
    const float* __restrict__ W,
    const float* __restrict__ bones,
    float* __restrict__ out,
    int n, int nv)
{
    extern __shared__ float smem[];
    float4* sv = reinterpret_cast<float4*>(smem);      // nv entries: (vx,vy,vz,|v|^2)
    float*  sB = smem + (size_t)nv * 4;                // 24*16 bone floats

    const int tid = threadIdx.x;

    // Cooperative load: pack verts with squared-norm (reference rounding: mul/add).
    for (int j = tid; j < nv; j += blockDim.x) {
        float vx = verts[3 * j + 0];
        float vy = verts[3 * j + 1];
        float vz = verts[3 * j + 2];
        float nv2 = __fadd_rn(__fadd_rn(__fmul_rn(vx, vx), __fmul_rn(vy, vy)),
                              __fmul_rn(vz, vz));
        sv[j] = make_float4(vx, vy, vz, nv2);
    }
    for (int j = tid; j < 24 * 16; j += blockDim.x) {
        sB[j] = bones[j];
    }
    __syncthreads();

    const int pt = blockIdx.x * blockDim.x + tid;
    if (pt >= n) return;

    const float px = xyz[3 * pt + 0];
    const float py = xyz[3 * pt + 1];
    const float pz = xyz[3 * pt + 2];

    // sx = sum(x*x) with mul/add rounding (matches XLA reduce; affects all j equally)
    const float sx = __fadd_rn(__fadd_rn(__fmul_rn(px, px), __fmul_rn(py, py)),
                               __fmul_rn(pz, pz));

    float best = 3.4e38f;
    int   bidx = 0;
    #pragma unroll 8
    for (int j = 0; j < nv; j++) {
        float4 v = sv[j];
        // dot = fma chain, accumulation order k=0,1,2 (SGEMM style)
        float dot = __fmaf_rn(px, v.x, 0.0f);
        dot = __fmaf_rn(py, v.y, dot);
        dot = __fmaf_rn(pz, v.z, dot);
        // (sx - 2*dot) rounds once == fma(-2, dot, sx); then + sv rounds once.
        float d2 = __fadd_rn(__fmaf_rn(-2.0f, dot, sx), v.w);
        bool lt = (d2 < best);         // strict <: first index wins ties (jnp.argmin)
        best = lt ? d2 : best;
        bidx = lt ? j : bidx;
    }

    // Blend bone transforms with the selected vertex's 24 skinning weights.
    float T[16];
    #pragma unroll
    for (int k = 0; k < 16; k++) T[k] = 0.0f;

    const float* wrow = W + (size_t)bidx * 24;
    #pragma unroll
    for (int j = 0; j < 24; j++) {
        float wj = __ldg(wrow + j);
        #pragma unroll
        for (int k = 0; k < 16; k++) {
            T[k] = fmaf(wj, sB[j * 16 + k], T[k]);
        }
    }

    // x_bar = T[:3,:] @ [x,1]
    float* out_x = out;
    #pragma unroll
    for (int i = 0; i < 3; i++) {
        float v = T[4 * i + 3];
        v = fmaf(T[4 * i + 0], px, v);
        v = fmaf(T[4 * i + 1], py, v);
        v = fmaf(T[4 * i + 2], pz, v);
        out_x[3 * pt + i] = v;
    }

    // Quaternion -> rotation matrix
    const float4 q = *reinterpret_cast<const float4*>(rot + 4 * pt);
    float qn = rsqrtf(q.x * q.x + q.y * q.y + q.z * q.z + q.w * q.w);
    float qr = q.x * qn, qx = q.y * qn, qy = q.z * qn, qz = q.w * qn;

    float R[3][3];
    R[0][0] = 1.0f - 2.0f * (qy * qy + qz * qz);
    R[0][1] = 2.0f * (qx * qy - qr * qz);
    R[0][2] = 2.0f * (qx * qz + qr * qy);
    R[1][0] = 2.0f * (qx * qy + qr * qz);
    R[1][1] = 1.0f - 2.0f * (qx * qx + qz * qz);
    R[1][2] = 2.0f * (qy * qz - qr * qx);
    R[2][0] = 2.0f * (qx * qz - qr * qy);
    R[2][1] = 2.0f * (qy * qz + qr * qx);
    R[2][2] = 1.0f - 2.0f * (qx * qx + qy * qy);

    // rotation_bar = T[:3,:3] @ R
    float* out_R = out + (size_t)3 * n;
    #pragma unroll
    for (int i = 0; i < 3; i++) {
        #pragma unroll
        for (int k = 0; k < 3; k++) {
            float v = T[4 * i + 0] * R[0][k];
            v = fmaf(T[4 * i + 1], R[1][k], v);
            v = fmaf(T[4 * i + 2], R[2][k], v);
            out_R[9 * pt + 3 * i + k] = v;
        }
    }

    // T_fwd (full 4x4)
    float4* out_T = reinterpret_cast<float4*>(out + (size_t)12 * n) + (size_t)4 * pt;
    #pragma unroll
    for (int k = 0; k < 4; k++) {
        out_T[k] = make_float4(T[4 * k + 0], T[4 * k + 1], T[4 * k + 2], T[4 * k + 3]);
    }
}

extern "C" void kernel_launch(void* const* d_in, const int* in_sizes, int n_in,
                              void* d_out, int out_size)
{
    const float* xyz   = (const float*)d_in[0];
    const float* rot   = (const float*)d_in[1];
    const float* verts = (const float*)d_in[2];
    const float* W     = (const float*)d_in[3];
    const float* bones = (const float*)d_in[4];
    float* out = (float*)d_out;

    const int n  = in_sizes[0] / 3;   // 100000
    const int nv = in_sizes[2] / 3;   // 6890

    const size_t smem = (size_t)nv * 16 + 24 * 16 * sizeof(float);
    cudaFuncSetAttribute(smpl_nn_kernel,
                         cudaFuncAttributeMaxDynamicSharedMemorySize, (int)smem);

    const int threads = 256;
    const int blocks  = (n + threads - 1) / threads;
    smpl_nn_kernel<<<blocks, threads, smem>>>(xyz, rot, verts, W, bones, out, n, nv);
}

// round 3
// speedup vs baseline: 1.3818x; 1.3818x over previous
#include <cuda_runtime.h>
#include <math_constants.h>

// SMPL nearest-neighbor skinning — packed-f32x2 argmin + rare-branch index recovery.
// Output layout: [0,3n) x_bar | [3n,12n) rotation_bar | [12n,28n) T_fwd
//
// d2 rounding matches reference exactly per lane:
//   dot = fma(pz, vz, fma(py, vy, mul(px, vx)))          (== fma chain with 0 seed)
//   d2  = add( fma(-2, dot, sx), |v|^2 )
// f32x2 ops are element-wise IEEE rn — identical to scalar FFMA/FADD.

typedef unsigned long long ull;

__device__ __forceinline__ ull f2_mul(ull a, ull b) {
    ull r; asm("mul.rn.f32x2 %0,%1,%2;" : "=l"(r) : "l"(a), "l"(b)); return r;
}
__device__ __forceinline__ ull f2_fma(ull a, ull b, ull c) {
    ull r; asm("fma.rn.f32x2 %0,%1,%2,%3;" : "=l"(r) : "l"(a), "l"(b), "l"(c)); return r;
}
__device__ __forceinline__ ull f2_add(ull a, ull b) {
    ull r; asm("add.rn.f32x2 %0,%1,%2;" : "=l"(r) : "l"(a), "l"(b)); return r;
}
__device__ __forceinline__ ull f2_pack(float lo, float hi) {
    ull r; asm("mov.b64 %0,{%1,%2};" : "=l"(r) : "f"(lo), "f"(hi)); return r;
}
__device__ __forceinline__ float2 f2_unpack(ull v) {
    float lo, hi; asm("mov.b64 {%0,%1},%2;" : "=f"(lo), "=f"(hi) : "l"(v));
    return make_float2(lo, hi);
}

static constexpr int NPAD = 6896;             // verts padded to multiple of 8
static constexpr int NPAIRS = NPAD / 2;       // 3448
static constexpr int NGROUPS = NPAD / 8;      // 862

__global__ void __launch_bounds__(384, 2) smpl_nn_kernel(
    const float* __restrict__ xyz,
    const float* __restrict__ rot,
    const float* __restrict__ verts,
    const float* __restrict__ W,
    const float* __restrict__ bones,
    float* __restrict__ out,
    int n, int nv)
{
    extern __shared__ float smem[];
    // Pair-packed verts: per pair p (verts 2p, 2p+1):
    //   sv4[2p]   = (vx0, vx1, vy0, vy1)
    //   sv4[2p+1] = (vz0, vz1, w0,  w1)   w = |v|^2 (mul/add rounding)
    float4* sv4 = reinterpret_cast<float4*>(smem);
    float*  sB  = smem + (size_t)NPAIRS * 8;          // 24*16 bone floats

    const int tid = threadIdx.x;

    for (int p = tid; p < NPAIRS; p += blockDim.x) {
        int j0 = 2 * p, j1 = 2 * p + 1;
        float x0 = 0.f, y0 = 0.f, z0 = 0.f, w0 = CUDART_INF_F;
        float x1 = 0.f, y1 = 0.f, z1 = 0.f, w1 = CUDART_INF_F;
        if (j0 < nv) {
            x0 = verts[3 * j0 + 0]; y0 = verts[3 * j0 + 1]; z0 = verts[3 * j0 + 2];
            w0 = __fadd_rn(__fadd_rn(__fmul_rn(x0, x0), __fmul_rn(y0, y0)),
                           __fmul_rn(z0, z0));
        }
        if (j1 < nv) {
            x1 = verts[3 * j1 + 0]; y1 = verts[3 * j1 + 1]; z1 = verts[3 * j1 + 2];
            w1 = __fadd_rn(__fadd_rn(__fmul_rn(x1, x1), __fmul_rn(y1, y1)),
                           __fmul_rn(z1, z1));
        }
        sv4[2 * p]     = make_float4(x0, x1, y0, y1);
        sv4[2 * p + 1] = make_float4(z0, z1, w0, w1);
    }
    for (int j = tid; j < 24 * 16; j += blockDim.x) sB[j] = bones[j];
    __syncthreads();

    const int pt = blockIdx.x * blockDim.x + tid;
    if (pt >= n) return;

    const float px = xyz[3 * pt + 0];
    const float py = xyz[3 * pt + 1];
    const float pz = xyz[3 * pt + 2];
    const float sx = __fadd_rn(__fadd_rn(__fmul_rn(px, px), __fmul_rn(py, py)),
                               __fmul_rn(pz, pz));

    const ull px2 = f2_pack(px, px);
    const ull py2 = f2_pack(py, py);
    const ull pz2 = f2_pack(pz, pz);
    const ull sx2 = f2_pack(sx, sx);
    const ull m2  = f2_pack(-2.0f, -2.0f);

    float best = CUDART_INF_F;
    int   bidx = 0;

    const ulonglong2* svp = reinterpret_cast<const ulonglong2*>(smem);

    for (int g = 0; g < NGROUPS; ++g) {
        const ulonglong2* q = svp + (size_t)g * 8;    // 4 pairs * 2 ulonglong2
        ull d2p[4];
        #pragma unroll
        for (int u = 0; u < 4; ++u) {
            ulonglong2 ab = q[2 * u];                 // (vx2, vy2)
            ulonglong2 cd = q[2 * u + 1];             // (vz2, w2)
            ull dot = f2_mul(px2, ab.x);
            dot = f2_fma(py2, ab.y, dot);
            dot = f2_fma(pz2, cd.x, dot);
            d2p[u] = f2_add(f2_fma(m2, dot, sx2), cd.y);
        }
        float2 a0 = f2_unpack(d2p[0]);
        float2 a1 = f2_unpack(d2p[1]);
        float2 a2 = f2_unpack(d2p[2]);
        float2 a3 = f2_unpack(d2p[3]);
        float gmin = fminf(fminf(fminf(a0.x, a0.y), fminf(a1.x, a1.y)),
                           fminf(fminf(a2.x, a2.y), fminf(a3.x, a3.y)));
        if (gmin < best) {                            // rare (~9 of 862 groups)
            float d[8] = {a0.x, a0.y, a1.x, a1.y, a2.x, a2.y, a3.x, a3.y};
            int j = g * 8;
            #pragma unroll
            for (int u = 0; u < 8; ++u) {
                if (d[u] < best) { best = d[u]; bidx = j + u; }  // first-wins
            }
        }
    }

    // Blend bone transforms with the selected vertex's 24 skinning weights.
    float T[16];
    #pragma unroll
    for (int k = 0; k < 16; ++k) T[k] = 0.0f;

    const float* wrow = W + (size_t)bidx * 24;
    #pragma unroll
    for (int j = 0; j < 24; ++j) {
        float wj = __ldg(wrow + j);
        #pragma unroll
        for (int k = 0; k < 16; ++k) T[k] = fmaf(wj, sB[j * 16 + k], T[k]);
    }

    // x_bar = T[:3,:] @ [x,1]
    #pragma unroll
    for (int i = 0; i < 3; ++i) {
        float v = T[4 * i + 3];
        v = fmaf(T[4 * i + 0], px, v);
        v = fmaf(T[4 * i + 1], py, v);
        v = fmaf(T[4 * i + 2], pz, v);
        out[3 * pt + i] = v;
    }

    // Quaternion -> rotation matrix
    const float4 q = *reinterpret_cast<const float4*>(rot + 4 * pt);
    float qn = rsqrtf(q.x * q.x + q.y * q.y + q.z * q.z + q.w * q.w);
    float qr = q.x * qn, qx = q.y * qn, qy = q.z * qn, qz = q.w * qn;

    float R[3][3];
    R[0][0] = 1.0f - 2.0f * (qy * qy + qz * qz);
    R[0][1] = 2.0f * (qx * qy - qr * qz);
    R[0][2] = 2.0f * (qx * qz + qr * qy);
    R[1][0] = 2.0f * (qx * qy + qr * qz);
    R[1][1] = 1.0f - 2.0f * (qx * qx + qz * qz);
    R[1][2] = 2.0f * (qy * qz - qr * qx);
    R[2][0] = 2.0f * (qx * qz - qr * qy);
    R[2][1] = 2.0f * (qy * qz + qr * qx);
    R[2][2] = 1.0f - 2.0f * (qx * qx + qy * qy);

    // rotation_bar = T[:3,:3] @ R
    float* out_R = out + (size_t)3 * n;
    #pragma unroll
    for (int i = 0; i < 3; ++i) {
        #pragma unroll
        for (int k = 0; k < 3; ++k) {
            float v = T[4 * i + 0] * R[0][k];
            v = fmaf(T[4 * i + 1], R[1][k], v);
            v = fmaf(T[4 * i + 2], R[2][k], v);
            out_R[9 * pt + 3 * i + k] = v;
        }
    }

    // T_fwd (full 4x4)
    float4* out_T = reinterpret_cast<float4*>(out + (size_t)12 * n) + (size_t)4 * pt;
    #pragma unroll
    for (int k = 0; k < 4; ++k)
        out_T[k] = make_float4(T[4 * k + 0], T[4 * k + 1], T[4 * k + 2], T[4 * k + 3]);
}

extern "C" void kernel_launch(void* const* d_in, const int* in_sizes, int n_in,
                              void* d_out, int out_size)
{
    const float* xyz   = (const float*)d_in[0];
    const float* rot   = (const float*)d_in[1];
    const float* verts = (const float*)d_in[2];
    const float* W     = (const float*)d_in[3];
    const float* bones = (const float*)d_in[4];
    float* out = (float*)d_out;

    const int n  = in_sizes[0] / 3;   // 100000
    const int nv = in_sizes[2] / 3;   // 6890

    const size_t smem = (size_t)NPAIRS * 8 * sizeof(float) + 24 * 16 * sizeof(float);
    cudaFuncSetAttribute(smpl_nn_kernel,
                         cudaFuncAttributeMaxDynamicSharedMemorySize, (int)smem);

    const int threads = 384;
    const int blocks  = (n + threads - 1) / threads;
    smpl_nn_kernel<<<blocks, threads, smem>>>(xyz, rot, verts, W, bones, out, n, nv);
}

// round 4
// speedup vs baseline: 1.4585x; 1.0555x over previous
#include <cuda_runtime.h>
#include <math_constants.h>

// SMPL nearest-neighbor skinning — packed-f32x2 argmin, 2 points/thread,
// grid-balanced single-wave launch (143 CTAs x 352 thr, 1 CTA/SM).
// Output layout: [0,3n) x_bar | [3n,12n) rotation_bar | [12n,28n) T_fwd
//
// d2 rounding matches reference exactly per lane:
//   dot = fma(pz, vz, fma(py, vy, mul(px, vx)))
//   d2  = add( fma(-2, dot, sx), |v|^2 )

typedef unsigned long long ull;

__device__ __forceinline__ ull f2_mul(ull a, ull b) {
    ull r; asm("mul.rn.f32x2 %0,%1,%2;" : "=l"(r) : "l"(a), "l"(b)); return r;
}
__device__ __forceinline__ ull f2_fma(ull a, ull b, ull c) {
    ull r; asm("fma.rn.f32x2 %0,%1,%2,%3;" : "=l"(r) : "l"(a), "l"(b), "l"(c)); return r;
}
__device__ __forceinline__ ull f2_add(ull a, ull b) {
    ull r; asm("add.rn.f32x2 %0,%1,%2;" : "=l"(r) : "l"(a), "l"(b)); return r;
}
__device__ __forceinline__ ull f2_pack(float lo, float hi) {
    ull r; asm("mov.b64 %0,{%1,%2};" : "=l"(r) : "f"(lo), "f"(hi)); return r;
}
__device__ __forceinline__ float2 f2_unpack(ull v) {
    float lo, hi; asm("mov.b64 {%0,%1},%2;" : "=f"(lo), "=f"(hi) : "l"(v));
    return make_float2(lo, hi);
}

static constexpr int NPAD = 6896;             // verts padded to multiple of 8
static constexpr int NPAIRS = NPAD / 2;       // 3448
static constexpr int NGROUPS = NPAD / 8;      // 862
static constexpr int THREADS = 352;           // 11 warps; grid<=148 => 1 CTA/SM

__device__ __forceinline__ void epilogue(
    int pt, int n, float px, float py, float pz, int bidx,
    const float* __restrict__ rot, const float* __restrict__ W,
    const float* __restrict__ sB, float* __restrict__ out)
{
    float T[16];
    #pragma unroll
    for (int k = 0; k < 16; ++k) T[k] = 0.0f;

    const float* wrow = W + (size_t)bidx * 24;
    #pragma unroll
    for (int j = 0; j < 24; ++j) {
        float wj = __ldg(wrow + j);
        #pragma unroll
        for (int k = 0; k < 16; ++k) T[k] = fmaf(wj, sB[j * 16 + k], T[k]);
    }

    // x_bar = T[:3,:] @ [x,1]
    #pragma unroll
    for (int i = 0; i < 3; ++i) {
        float v = T[4 * i + 3];
        v = fmaf(T[4 * i + 0], px, v);
        v = fmaf(T[4 * i + 1], py, v);
        v = fmaf(T[4 * i + 2], pz, v);
        out[3 * pt + i] = v;
    }

    // Quaternion -> rotation matrix
    const float4 q = *reinterpret_cast<const float4*>(rot + 4 * pt);
    float qn = rsqrtf(q.x * q.x + q.y * q.y + q.z * q.z + q.w * q.w);
    float qr = q.x * qn, qx = q.y * qn, qy = q.z * qn, qz = q.w * qn;

    float R[3][3];
    R[0][0] = 1.0f - 2.0f * (qy * qy + qz * qz);
    R[0][1] = 2.0f * (qx * qy - qr * qz);
    R[0][2] = 2.0f * (qx * qz + qr * qy);
    R[1][0] = 2.0f * (qx * qy + qr * qz);
    R[1][1] = 1.0f - 2.0f * (qx * qx + qz * qz);
    R[1][2] = 2.0f * (qy * qz - qr * qx);
    R[2][0] = 2.0f * (qx * qz - qr * qy);
    R[2][1] = 2.0f * (qy * qz + qr * qx);
    R[2][2] = 1.0f - 2.0f * (qx * qx + qy * qy);

    // rotation_bar = T[:3,:3] @ R
    float* out_R = out + (size_t)3 * n;
    #pragma unroll
    for (int i = 0; i < 3; ++i) {
        #pragma unroll
        for (int k = 0; k < 3; ++k) {
            float v = T[4 * i + 0] * R[0][k];
            v = fmaf(T[4 * i + 1], R[1][k], v);
            v = fmaf(T[4 * i + 2], R[2][k], v);
            out_R[9 * pt + 3 * i + k] = v;
        }
    }

    // T_fwd (full 4x4)
    float4* out_T = reinterpret_cast<float4*>(out + (size_t)12 * n) + (size_t)4 * pt;
    #pragma unroll
    for (int k = 0; k < 4; ++k)
        out_T[k] = make_float4(T[4 * k + 0], T[4 * k + 1], T[4 * k + 2], T[4 * k + 3]);
}

__global__ void __launch_bounds__(THREADS, 1) smpl_nn_kernel(
    const float* __restrict__ xyz,
    const float* __restrict__ rot,
    const float* __restrict__ verts,
    const float* __restrict__ W,
    const float* __restrict__ bones,
    float* __restrict__ out,
    int n, int nv)
{
    extern __shared__ float smem[];
    // Pair-packed verts: per pair p (verts 2p, 2p+1):
    //   sv4[2p]   = (vx0, vx1, vy0, vy1)
    //   sv4[2p+1] = (vz0, vz1, w0,  w1)   w = |v|^2 (mul/add rounding)
    float4* sv4 = reinterpret_cast<float4*>(smem);
    float*  sB  = smem + (size_t)NPAIRS * 8;          // 24*16 bone floats

    const int tid = threadIdx.x;

    for (int p = tid; p < NPAIRS; p += THREADS) {
        int j0 = 2 * p, j1 = 2 * p + 1;
        float x0 = 0.f, y0 = 0.f, z0 = 0.f, w0 = CUDART_INF_F;
        float x1 = 0.f, y1 = 0.f, z1 = 0.f, w1 = CUDART_INF_F;
        if (j0 < nv) {
            x0 = verts[3 * j0 + 0]; y0 = verts[3 * j0 + 1]; z0 = verts[3 * j0 + 2];
            w0 = __fadd_rn(__fadd_rn(__fmul_rn(x0, x0), __fmul_rn(y0, y0)),
                           __fmul_rn(z0, z0));
        }
        if (j1 < nv) {
            x1 = verts[3 * j1 + 0]; y1 = verts[3 * j1 + 1]; z1 = verts[3 * j1 + 2];
            w1 = __fadd_rn(__fadd_rn(__fmul_rn(x1, x1), __fmul_rn(y1, y1)),
                           __fmul_rn(z1, z1));
        }
        sv4[2 * p]     = make_float4(x0, x1, y0, y1);
        sv4[2 * p + 1] = make_float4(z0, z1, w0, w1);
    }
    for (int j = tid; j < 24 * 16; j += THREADS) sB[j] = bones[j];
    __syncthreads();

    // Two consecutive points per thread.
    const int t   = blockIdx.x * THREADS + tid;
    const int pt0 = 2 * t;
    const int pt1 = 2 * t + 1;
    if (pt0 >= n) return;
    const int pt1c = (pt1 < n) ? pt1 : pt0;   // clamp reads for tail thread

    const float px0 = xyz[3 * pt0 + 0], py0 = xyz[3 * pt0 + 1], pz0 = xyz[3 * pt0 + 2];
    const float px1 = xyz[3 * pt1c + 0], py1 = xyz[3 * pt1c + 1], pz1 = xyz[3 * pt1c + 2];

    const float sx0 = __fadd_rn(__fadd_rn(__fmul_rn(px0, px0), __fmul_rn(py0, py0)),
                                __fmul_rn(pz0, pz0));
    const float sx1 = __fadd_rn(__fadd_rn(__fmul_rn(px1, px1), __fmul_rn(py1, py1)),
                                __fmul_rn(pz1, pz1));

    const ull Px0 = f2_pack(px0, px0), Py0 = f2_pack(py0, py0), Pz0 = f2_pack(pz0, pz0);
    const ull Px1 = f2_pack(px1, px1), Py1 = f2_pack(py1, py1), Pz1 = f2_pack(pz1, pz1);
    const ull Sx0 = f2_pack(sx0, sx0), Sx1 = f2_pack(sx1, sx1);
    const ull M2  = f2_pack(-2.0f, -2.0f);

    float best0 = CUDART_INF_F, best1 = CUDART_INF_F;
    int   bidx0 = 0,            bidx1 = 0;

    const ulonglong2* svp = reinterpret_cast<const ulonglong2*>(smem);

    for (int g = 0; g < NGROUPS; ++g) {
        const ulonglong2* q = svp + (size_t)g * 8;    // 4 pairs * 2 ulonglong2
        ull d0p[4], d1p[4];
        #pragma unroll
        for (int u = 0; u < 4; ++u) {
            ulonglong2 ab = q[2 * u];                 // (vx2, vy2)
            ulonglong2 cd = q[2 * u + 1];             // (vz2, w2)
            ull dot0 = f2_mul(Px0, ab.x);
            ull dot1 = f2_mul(Px1, ab.x);
            dot0 = f2_fma(Py0, ab.y, dot0);
            dot1 = f2_fma(Py1, ab.y, dot1);
            dot0 = f2_fma(Pz0, cd.x, dot0);
            dot1 = f2_fma(Pz1, cd.x, dot1);
            d0p[u] = f2_add(f2_fma(M2, dot0, Sx0), cd.y);
            d1p[u] = f2_add(f2_fma(M2, dot1, Sx1), cd.y);
        }
        float2 a0 = f2_unpack(d0p[0]), a1 = f2_unpack(d0p[1]);
        float2 a2 = f2_unpack(d0p[2]), a3 = f2_unpack(d0p[3]);
        float2 b0 = f2_unpack(d1p[0]), b1 = f2_unpack(d1p[1]);
        float2 b2 = f2_unpack(d1p[2]), b3 = f2_unpack(d1p[3]);

        float g0 = fminf(fminf(fminf(a0.x, a0.y), fminf(a1.x, a1.y)),
                         fminf(fminf(a2.x, a2.y), fminf(a3.x, a3.y)));
        float g1 = fminf(fminf(fminf(b0.x, b0.y), fminf(b1.x, b1.y)),
                         fminf(fminf(b2.x, b2.y), fminf(b3.x, b3.y)));

        if (g0 < best0) {                             // rare
            float d[8] = {a0.x, a0.y, a1.x, a1.y, a2.x, a2.y, a3.x, a3.y};
            int j = g * 8;
            #pragma unroll
            for (int u = 0; u < 8; ++u)
                if (d[u] < best0) { best0 = d[u]; bidx0 = j + u; }   // first-wins
        }
        if (g1 < best1) {                             // rare
            float d[8] = {b0.x, b0.y, b1.x, b1.y, b2.x, b2.y, b3.x, b3.y};
            int j = g * 8;
            #pragma unroll
            for (int u = 0; u < 8; ++u)
                if (d[u] < best1) { best1 = d[u]; bidx1 = j + u; }
        }
    }

    epilogue(pt0, n, px0, py0, pz0, bidx0, rot, W, sB, out);
    if (pt1 < n)
        epilogue(pt1, n, px1, py1, pz1, bidx1, rot, W, sB, out);
}

extern "C" void kernel_launch(void* const* d_in, const int* in_sizes, int n_in,
                              void* d_out, int out_size)
{
    const float* xyz   = (const float*)d_in[0];
    const float* rot   = (const float*)d_in[1];
    const float* verts = (const float*)d_in[2];
    const float* W     = (const float*)d_in[3];
    const float* bones = (const float*)d_in[4];
    float* out = (float*)d_out;

    const int n  = in_sizes[0] / 3;   // 100000
    const int nv = in_sizes[2] / 3;   // 6890

    const size_t smem = (size_t)NPAIRS * 8 * sizeof(float) + 24 * 16 * sizeof(float);
    cudaFuncSetAttribute(smpl_nn_kernel,
                         cudaFuncAttributeMaxDynamicSharedMemorySize, (int)smem);

    const int nthreads = (n + 1) / 2;                    // one thread per 2 points
    const int blocks   = (nthreads + THREADS - 1) / THREADS;  // 143 for n=100000
    smpl_nn_kernel<<<blocks, THREADS, smem>>>(xyz, rot, verts, W, bones, out, n, nv);
}

// round 5
// speedup vs baseline: 1.8296x; 1.2545x over previous
#include <cuda_runtime.h>
#include <math_constants.h>

// SMPL nearest-neighbor skinning — packed-f32x2 argmin, 2 points/thread,
// BRANCHLESS group argmin (best value + group id via SEL), index recovered
// post-loop by recomputing one group. 143 CTAs x 352 thr, 1 CTA/SM.
// Output layout: [0,3n) x_bar | [3n,12n) rotation_bar | [12n,28n) T_fwd
//
// d2 rounding matches reference exactly per lane:
//   dot = fma(pz, vz, fma(py, vy, mul(px, vx)))
//   d2  = add( fma(-2, dot, sx), |v|^2 )

typedef unsigned long long ull;

__device__ __forceinline__ ull f2_mul(ull a, ull b) {
    ull r; asm("mul.rn.f32x2 %0,%1,%2;" : "=l"(r) : "l"(a), "l"(b)); return r;
}
__device__ __forceinline__ ull f2_fma(ull a, ull b, ull c) {
    ull r; asm("fma.rn.f32x2 %0,%1,%2,%3;" : "=l"(r) : "l"(a), "l"(b), "l"(c)); return r;
}
__device__ __forceinline__ ull f2_add(ull a, ull b) {
    ull r; asm("add.rn.f32x2 %0,%1,%2;" : "=l"(r) : "l"(a), "l"(b)); return r;
}
__device__ __forceinline__ ull f2_pack(float lo, float hi) {
    ull r; asm("mov.b64 %0,{%1,%2};" : "=l"(r) : "f"(lo), "f"(hi)); return r;
}
__device__ __forceinline__ float2 f2_unpack(ull v) {
    float lo, hi; asm("mov.b64 {%0,%1},%2;" : "=f"(lo), "=f"(hi) : "l"(v));
    return make_float2(lo, hi);
}

static constexpr int NPAD = 6896;             // verts padded to multiple of 8
static constexpr int NPAIRS = NPAD / 2;       // 3448
static constexpr int NGROUPS = NPAD / 8;      // 862
static constexpr int THREADS = 352;           // 11 warps; grid<=148 => 1 CTA/SM

// Compute the 8 d2 values of one group (exact reference rounding).
__device__ __forceinline__ void group_d2(
    const ulonglong2* __restrict__ q, ull Px, ull Py, ull Pz, ull Sx, ull M2,
    float2* a /*4 entries*/)
{
    #pragma unroll
    for (int u = 0; u < 4; ++u) {
        ulonglong2 ab = q[2 * u];                 // (vx2, vy2)
        ulonglong2 cd = q[2 * u + 1];             // (vz2, w2)
        ull dot = f2_mul(Px, ab.x);
        dot = f2_fma(Py, ab.y, dot);
        dot = f2_fma(Pz, cd.x, dot);
        a[u] = f2_unpack(f2_add(f2_fma(M2, dot, Sx), cd.y));
    }
}

__device__ __forceinline__ void epilogue(
    int pt, int n, float px, float py, float pz, int bidx,
    const float* __restrict__ rot, const float* __restrict__ W,
    const float* __restrict__ sB, float* __restrict__ out)
{
    float T[16];
    #pragma unroll
    for (int k = 0; k < 16; ++k) T[k] = 0.0f;

    const float* wrow = W + (size_t)bidx * 24;
    #pragma unroll
    for (int j = 0; j < 24; ++j) {
        float wj = __ldg(wrow + j);
        #pragma unroll
        for (int k = 0; k < 16; ++k) T[k] = fmaf(wj, sB[j * 16 + k], T[k]);
    }

    // x_bar = T[:3,:] @ [x,1]
    #pragma unroll
    for (int i = 0; i < 3; ++i) {
        float v = T[4 * i + 3];
        v = fmaf(T[4 * i + 0], px, v);
        v = fmaf(T[4 * i + 1], py, v);
        v = fmaf(T[4 * i + 2], pz, v);
        out[3 * pt + i] = v;
    }

    // Quaternion -> rotation matrix
    const float4 q = *reinterpret_cast<const float4*>(rot + 4 * pt);
    float qn = rsqrtf(q.x * q.x + q.y * q.y + q.z * q.z + q.w * q.w);
    float qr = q.x * qn, qx = q.y * qn, qy = q.z * qn, qz = q.w * qn;

    float R[3][3];
    R[0][0] = 1.0f - 2.0f * (qy * qy + qz * qz);
    R[0][1] = 2.0f * (qx * qy - qr * qz);
    R[0][2] = 2.0f * (qx * qz + qr * qy);
    R[1][0] = 2.0f * (qx * qy + qr * qz);
    R[1][1] = 1.0f - 2.0f * (qx * qx + qz * qz);
    R[1][2] = 2.0f * (qy * qz - qr * qx);
    R[2][0] = 2.0f * (qx * qz - qr * qy);
    R[2][1] = 2.0f * (qy * qz + qr * qx);
    R[2][2] = 1.0f - 2.0f * (qx * qx + qy * qy);

    // rotation_bar = T[:3,:3] @ R
    float* out_R = out + (size_t)3 * n;
    #pragma unroll
    for (int i = 0; i < 3; ++i) {
        #pragma unroll
        for (int k = 0; k < 3; ++k) {
            float v = T[4 * i + 0] * R[0][k];
            v = fmaf(T[4 * i + 1], R[1][k], v);
            v = fmaf(T[4 * i + 2], R[2][k], v);
            out_R[9 * pt + 3 * i + k] = v;
        }
    }

    // T_fwd (full 4x4)
    float4* out_T = reinterpret_cast<float4*>(out + (size_t)12 * n) + (size_t)4 * pt;
    #pragma unroll
    for (int k = 0; k < 4; ++k)
        out_T[k] = make_float4(T[4 * k + 0], T[4 * k + 1], T[4 * k + 2], T[4 * k + 3]);
}

__global__ void __launch_bounds__(THREADS, 1) smpl_nn_kernel(
    const float* __restrict__ xyz,
    const float* __restrict__ rot,
    const float* __restrict__ verts,
    const float* __restrict__ W,
    const float* __restrict__ bones,
    float* __restrict__ out,
    int n, int nv)
{
    extern __shared__ float smem[];
    // Pair-packed verts: per pair p (verts 2p, 2p+1):
    //   sv4[2p]   = (vx0, vx1, vy0, vy1)
    //   sv4[2p+1] = (vz0, vz1, w0,  w1)   w = |v|^2 (mul/add rounding)
    float4* sv4 = reinterpret_cast<float4*>(smem);
    float*  sB  = smem + (size_t)NPAIRS * 8;          // 24*16 bone floats

    const int tid = threadIdx.x;

    for (int p = tid; p < NPAIRS; p += THREADS) {
        int j0 = 2 * p, j1 = 2 * p + 1;
        float x0 = 0.f, y0 = 0.f, z0 = 0.f, w0 = CUDART_INF_F;
        float x1 = 0.f, y1 = 0.f, z1 = 0.f, w1 = CUDART_INF_F;
        if (j0 < nv) {
            x0 = verts[3 * j0 + 0]; y0 = verts[3 * j0 + 1]; z0 = verts[3 * j0 + 2];
            w0 = __fadd_rn(__fadd_rn(__fmul_rn(x0, x0), __fmul_rn(y0, y0)),
                           __fmul_rn(z0, z0));
        }
        if (j1 < nv) {
            x1 = verts[3 * j1 + 0]; y1 = verts[3 * j1 + 1]; z1 = verts[3 * j1 + 2];
            w1 = __fadd_rn(__fadd_rn(__fmul_rn(x1, x1), __fmul_rn(y1, y1)),
                           __fmul_rn(z1, z1));
        }
        sv4[2 * p]     = make_float4(x0, x1, y0, y1);
        sv4[2 * p + 1] = make_float4(z0, z1, w0, w1);
    }
    for (int j = tid; j < 24 * 16; j += THREADS) sB[j] = bones[j];
    __syncthreads();

    // Two consecutive points per thread.
    const int t   = blockIdx.x * THREADS + tid;
    const int pt0 = 2 * t;
    const int pt1 = 2 * t + 1;
    if (pt0 >= n) return;
    const int pt1c = (pt1 < n) ? pt1 : pt0;   // clamp reads for tail thread

    const float px0 = xyz[3 * pt0 + 0], py0 = xyz[3 * pt0 + 1], pz0 = xyz[3 * pt0 + 2];
    const float px1 = xyz[3 * pt1c + 0], py1 = xyz[3 * pt1c + 1], pz1 = xyz[3 * pt1c + 2];

    const float sx0 = __fadd_rn(__fadd_rn(__fmul_rn(px0, px0), __fmul_rn(py0, py0)),
                                __fmul_rn(pz0, pz0));
    const float sx1 = __fadd_rn(__fadd_rn(__fmul_rn(px1, px1), __fmul_rn(py1, py1)),
                                __fmul_rn(pz1, pz1));

    const ull Px0 = f2_pack(px0, px0), Py0 = f2_pack(py0, py0), Pz0 = f2_pack(pz0, pz0);
    const ull Px1 = f2_pack(px1, px1), Py1 = f2_pack(py1, py1), Pz1 = f2_pack(pz1, pz1);
    const ull Sx0 = f2_pack(sx0, sx0), Sx1 = f2_pack(sx1, sx1);
    const ull M2  = f2_pack(-2.0f, -2.0f);

    float best0 = CUDART_INF_F, best1 = CUDART_INF_F;
    int   bg0 = 0, bg1 = 0;                       // best GROUP per point

    const ulonglong2* svp = reinterpret_cast<const ulonglong2*>(smem);

    #pragma unroll 2
    for (int g = 0; g < NGROUPS; ++g) {
        const ulonglong2* q = svp + (size_t)g * 8;    // 4 pairs * 2 ulonglong2
        float2 a[4], b[4];
        group_d2(q, Px0, Py0, Pz0, Sx0, M2, a);
        group_d2(q, Px1, Py1, Pz1, Sx1, M2, b);

        float g0 = fminf(fminf(fminf(a[0].x, a[0].y), fminf(a[1].x, a[1].y)),
                         fminf(fminf(a[2].x, a[2].y), fminf(a[3].x, a[3].y)));
        float g1 = fminf(fminf(fminf(b[0].x, b[0].y), fminf(b[1].x, b[1].y)),
                         fminf(fminf(b[2].x, b[2].y), fminf(b[3].x, b[3].y)));

        // Branchless: strict < keeps FIRST group attaining the running min.
        bool c0 = (g0 < best0);
        bool c1 = (g1 < best1);
        best0 = c0 ? g0 : best0;
        bg0   = c0 ? g  : bg0;
        best1 = c1 ? g1 : best1;
        bg1   = c1 ? g  : bg1;
    }

    // Post-loop: recover the first index within the winning group.
    int bidx0, bidx1;
    {
        float2 a[4];
        group_d2(svp + (size_t)bg0 * 8, Px0, Py0, Pz0, Sx0, M2, a);
        float d[8] = {a[0].x, a[0].y, a[1].x, a[1].y, a[2].x, a[2].y, a[3].x, a[3].y};
        int off = 0;
        #pragma unroll
        for (int u = 7; u >= 0; --u)
            if (d[u] == best0) off = u;           // descending -> lowest match wins
        bidx0 = bg0 * 8 + off;
    }
    {
        float2 b[4];
        group_d2(svp + (size_t)bg1 * 8, Px1, Py1, Pz1, Sx1, M2, b);
        float d[8] = {b[0].x, b[0].y, b[1].x, b[1].y, b[2].x, b[2].y, b[3].x, b[3].y};
        int off = 0;
        #pragma unroll
        for (int u = 7; u >= 0; --u)
            if (d[u] == best1) off = u;
        bidx1 = bg1 * 8 + off;
    }

    epilogue(pt0, n, px0, py0, pz0, bidx0, rot, W, sB, out);
    if (pt1 < n)
        epilogue(pt1, n, px1, py1, pz1, bidx1, rot, W, sB, out);
}

extern "C" void kernel_launch(void* const* d_in, const int* in_sizes, int n_in,
                              void* d_out, int out_size)
{
    const float* xyz   = (const float*)d_in[0];
    const float* rot   = (const float*)d_in[1];
    const float* verts = (const float*)d_in[2];
    const float* W     = (const float*)d_in[3];
    const float* bones = (const float*)d_in[4];
    float* out = (float*)d_out;

    const int n  = in_sizes[0] / 3;   // 100000
    const int nv = in_sizes[2] / 3;   // 6890

    const size_t smem = (size_t)NPAIRS * 8 * sizeof(float) + 24 * 16 * sizeof(float);
    cudaFuncSetAttribute(smpl_nn_kernel,
                         cudaFuncAttributeMaxDynamicSharedMemorySize, (int)smem);

    const int nthreads = (n + 1) / 2;                         // one thread per 2 points
    const int blocks   = (nthreads + THREADS - 1) / THREADS;  // 143 for n=100000
    smpl_nn_kernel<<<blocks, THREADS, smem>>>(xyz, rot, verts, W, bones, out, n, nv);
}